// round 1
// baseline (speedup 1.0000x reference)
#include <cuda_runtime.h>

// QuantumParity analytic reduction:
//   feats are Heisenberg-evolved parity expectations of a product state:
//     feat_k     = prod_{q=0..k}   cos(x_q)          (k = 0..7)
//     feat_(i,j) = prod_{q=i+1..j} cos(x_q)          (i<j, 28 pairs)
//   out[c] = b[c] + sum_f W[c][f] * feat_f
//
// Per row: 8 polynomial cosines + 28 window products + 72 FMAs. No 256-dim
// statevector, no feature matrix, no MUFU.

#define NQ 8
#define NFEAT 36   // 8 + 28

__device__ __forceinline__ float cos_poly(float x) {
    // x in [0, pi]; t = x - pi/2 in [-pi/2, pi/2]; cos(x) = -sin(t).
    // Taylor of sin to t^11: truncation < 6e-8 on this range.
    float t = x - 1.57079632679489662f;
    float u = t * t;
    float p = fmaf(u, -2.50521084e-8f, 2.75573192e-6f);
    p = fmaf(u, p, -1.98412698e-4f);
    p = fmaf(u, p, 8.33333333e-3f);
    p = fmaf(u, p, -1.66666667e-1f);
    p = fmaf(u, p, 1.0f);
    return (-t) * p;
}

__global__ void __launch_bounds__(256)
quantum_parity_kernel(const float* __restrict__ x,
                      const float* __restrict__ W,
                      const float* __restrict__ bias,
                      float* __restrict__ out,
                      int nrows) {
    __shared__ float sW[2 * NFEAT + 2];
    int tid = threadIdx.x;
    if (tid < 2 * NFEAT) sW[tid] = W[tid];
    if (tid < 2) sW[2 * NFEAT + tid] = bias[tid];
    __syncthreads();

    int row = blockIdx.x * blockDim.x + tid;
    if (row >= nrows) return;

    // 8 contiguous fp32 angles per row: two float4 loads (32B aligned).
    const float4* xp = reinterpret_cast<const float4*>(x + (size_t)row * NQ);
    float4 a = xp[0];
    float4 d = xp[1];

    float c[NQ];
    c[0] = cos_poly(a.x);
    c[1] = cos_poly(a.y);
    c[2] = cos_poly(a.z);
    c[3] = cos_poly(a.w);
    c[4] = cos_poly(d.x);
    c[5] = cos_poly(d.y);
    c[6] = cos_poly(d.z);
    c[7] = cos_poly(d.w);

    float acc0 = sW[2 * NFEAT + 0];
    float acc1 = sW[2 * NFEAT + 1];

    // Single-Z features: prefix products P_k = c0*...*ck
    float p = 1.0f;
#pragma unroll
    for (int k = 0; k < NQ; k++) {
        p *= c[k];
        acc0 = fmaf(sW[k], p, acc0);
        acc1 = fmaf(sW[NFEAT + k], p, acc1);
    }

    // Pair features (i<j): window products c_{i+1}*...*c_j
    int f = NQ;
#pragma unroll
    for (int i = 0; i < NQ; i++) {
        float q = 1.0f;
#pragma unroll
        for (int j = i + 1; j < NQ; j++) {
            q *= c[j];
            acc0 = fmaf(sW[f], q, acc0);
            acc1 = fmaf(sW[NFEAT + f], q, acc1);
            f++;
        }
    }

    reinterpret_cast<float2*>(out)[row] = make_float2(acc0, acc1);
}

extern "C" void kernel_launch(void* const* d_in, const int* in_sizes, int n_in,
                              void* d_out, int out_size) {
    const float* x    = (const float*)d_in[0];   // (B, 8) fp32
    const float* W    = (const float*)d_in[1];   // (2, 36) fp32
    const float* bias = (const float*)d_in[2];   // (2,) fp32

    int nrows = in_sizes[0] / NQ;                // 131072
    float* out = (float*)d_out;                  // (B, 2) fp32

    int block = 256;
    int grid = (nrows + block - 1) / block;
    quantum_parity_kernel<<<grid, block>>>(x, W, bias, out, nrows);
}